// round 7
// baseline (speedup 1.0000x reference)
#include <cuda_runtime.h>
#include <cuda_fp16.h>
#include <cstdint>

#define B_ 256
#define T_ 512
#define D_ 512
#define H_ 256
#define V_ 512

// ---------------- persistent device scratch --------------------------------
__device__ float    g_embWp[2][V_][1024];             // emb@W + b, gate-permuted cols (fp32)
__device__ uint4    g_Uf16[2 * 8 * 16 * 4 * 2 * 32];  // U fp16 b-frags [d][nc][kc16][wn4][p2][lane]
__device__ uint4    g_HA4[2 * 2 * 8 * 1024];          // final h publish (only s=511) for output kernel

// ---------------- helpers --------------------------------------------------
__device__ __forceinline__ float tapx(float x) {
    float r; asm("tanh.approx.f32 %0, %1;" : "=f"(r) : "f"(x));
    return r;
}
__device__ __forceinline__ float sigx(float x) { return fmaf(tapx(0.5f * x), 0.5f, 0.5f); }
__device__ __forceinline__ void mma16(float* c, const unsigned* a, unsigned b0, unsigned b1) {
    asm volatile(
        "mma.sync.aligned.m16n8k16.row.col.f32.f16.f16.f32 "
        "{%0,%1,%2,%3}, {%4,%5,%6,%7}, {%8,%9}, {%0,%1,%2,%3};\n"
        : "+f"(c[0]), "+f"(c[1]), "+f"(c[2]), "+f"(c[3])
        : "r"(a[0]), "r"(a[1]), "r"(a[2]), "r"(a[3]), "r"(b0), "r"(b1));
}
__device__ __forceinline__ uint32_t smem_u32(const void* p) {
    uint32_t a;
    asm("{ .reg .u64 t; cvta.to.shared.u64 t, %1; cvt.u32.u64 %0, t; }" : "=r"(a) : "l"(p));
    return a;
}
__device__ __forceinline__ void mbar_wait_cluster(uint32_t bar, unsigned ph) {
    unsigned done;
    do {
        asm volatile(
            "{ .reg .pred p;\n"
            "  mbarrier.try_wait.parity.acquire.cluster.shared::cta.b64 p, [%1], %2, 0x989680;\n"
            "  selp.b32 %0, 1, 0, p; }"
            : "=r"(done) : "r"(bar), "r"(ph) : "memory");
    } while (!done);
}
__host__ __device__ __forceinline__ int perm_col(int gate, int j) {
    return (j >> 5) * 128 + ((j >> 3) & 3) * 32 + ((j >> 1) & 3) * 8
         + (gate >> 1) * 4 + (j & 1) * 2 + (gate & 1);
}

// ---------------- kernel 1: embW precompute (permuted cols, fp32) ----------
__global__ void precompute_embW(const float* __restrict__ emb,
                                const float* __restrict__ W_f, const float* __restrict__ b_f,
                                const float* __restrict__ W_b, const float* __restrict__ b_b) {
    const int d = blockIdx.z;
    const float* W  = d ? W_b : W_f;
    const float* bv = d ? b_b : b_f;
    const int oc = blockIdx.x * 64 + (threadIdx.x & 63);
    const int v0 = blockIdx.y * 16;
    __shared__ float sE[16 * 512];
    for (int i = threadIdx.x; i < 16 * 512; i += 256) sE[i] = emb[v0 * 512 + i];
    __syncthreads();
    const int vq = threadIdx.x >> 6;
    float acc[4] = {0.f, 0.f, 0.f, 0.f};
    for (int k = 0; k < 512; k++) {
        float wv = W[k * 1024 + oc];
#pragma unroll
        for (int i = 0; i < 4; i++) acc[i] += sE[(vq * 4 + i) * 512 + k] * wv;
    }
    const int gate = oc >> 8, j = oc & 255;
    const int pcol = perm_col(gate, j);
    const float bb = bv[oc];
#pragma unroll
    for (int i = 0; i < 4; i++)
        g_embWp[d][v0 + vq * 4 + i][pcol] = acc[i] + bb;
}

// ---------------- kernel 2: U -> fp16 b-frag layout ------------------------
__global__ void build_Uf16(const float* __restrict__ U_f, const float* __restrict__ U_b) {
    int t = blockIdx.x * blockDim.x + threadIdx.x;
    if (t >= 65536) return;
    const int lane = t & 31;
    const int p    = (t >> 5) & 1;
    const int w    = (t >> 6) & 3;
    const int kc   = (t >> 8) & 15;
    const int nc   = (t >> 12) & 7;
    const int d    = (t >> 15) & 1;
    const float* U = d ? U_b : U_f;
    const int l4 = lane & 3, ld4 = lane >> 2;
    const int o8 = ld4;
    const int gate = (o8 & 1) + 2 * (o8 >> 2);
    const int uSel = (o8 >> 1) & 1;
    unsigned vals[4];
#pragma unroll
    for (int i = 0; i < 4; i++) {
        const int ns = 2 * p + (i >> 1);
        const int k0 = kc * 16 + l4 * 2 + (i & 1) * 8;
        const int j  = nc * 32 + w * 8 + ns * 2 + uSel;
        const int col = gate * 256 + j;
        unsigned h0 = (unsigned)__half_as_ushort(__float2half_rn(U[k0 * 1024 + col]));
        unsigned h1 = (unsigned)__half_as_ushort(__float2half_rn(U[(k0 + 1) * 1024 + col]));
        vals[i] = h0 | (h1 << 16);
    }
    g_Uf16[t] = make_uint4(vals[0], vals[1], vals[2], vals[3]);
}

// ---------------- kernel 3: persistent recurrence, DSMEM cluster exchange --
// grid = 128 = 16 clusters of 8. cluster covers nc = 0..7 for one (d, m).
// block = 256 = 8 warps (w_m 2 x w_n 4).
__global__ void __launch_bounds__(256, 1) __cluster_dims__(8, 1, 1)
lstm_kernel(const int* __restrict__ token_ids) {
    extern __shared__ uint4 smem4[];
    uint4* sU   = smem4;           // 4096 uint4 = 64KB: U b-frags
    uint4* sBuf = smem4 + 4096;    // 2048 uint4 = 32KB: A-frag rings [par2][slot32][lane32]
    __shared__ __align__(16) unsigned long long mbarArr[4];   // [w_m*2 + par]

    const int tid = threadIdx.x;
    const int bx  = blockIdx.x;
    const int cid = bx >> 3;
    const int d   = cid >> 3;
    const int m   = cid & 7;
    const int nc  = bx & 7;            // == cluster ctarank (1-D cluster of 8)
    const int wid = tid >> 5;
    const int w_n = wid & 3;
    const int w_m = wid >> 2;
    const int l   = tid & 31;
    const int l4  = l & 3, ld4 = l >> 2;
    const bool hi4 = (l4 >= 2);

    const uint32_t barBase = smem_u32(&mbarArr[0]);
    const uint32_t bufBase = smem_u32(sBuf);

    if (tid == 0) {
#pragma unroll
        for (int i = 0; i < 4; i++)
            asm volatile("mbarrier.init.shared.b64 [%0], %1;"
                         :: "r"(barBase + i * 8), "r"(512u) : "memory");
    }
    {   // load U slice
        const uint4* src = &g_Uf16[(d * 8 + nc) * 4096];
        for (int i = tid; i < 4096; i += 256) sU[i] = src[i];
    }
    __syncthreads();
    asm volatile("barrier.cluster.arrive.aligned;" ::: "memory");
    asm volatile("barrier.cluster.wait.aligned;" ::: "memory");

    // precompute DSMEM base addresses of all 8 peers
    uint32_t rbuf[8], rbar[8];
#pragma unroll
    for (int r = 0; r < 8; r++) {
        asm("mapa.shared::cluster.u32 %0, %1, %2;" : "=r"(rbuf[r]) : "r"(bufBase), "r"(r));
        asm("mapa.shared::cluster.u32 %0, %1, %2;" : "=r"(rbar[r]) : "r"(barBase), "r"(r));
    }

    float cs[4], hs[4];
#pragma unroll
    for (int a = 0; a < 4; a++) { cs[a] = 0.f; hs[a] = 0.f; }

    const int rbase = m * 32;
    const int kcP  = nc * 2 + (w_n >> 1);
    const int regP = (hi4 ? 1 : 0) + ((w_n & 1) ? 2 : 0);
    const int r0   = (l4 & 1) * 4;     // this lane's 4 DSMEM targets

    for (int s = 0; s < T_; s++) {
        const int tt = d ? (T_ - 1 - s) : s;

        const int row0 = rbase + w_m * 16 + ld4;
        const int t0 = token_ids[row0 * T_ + tt];
        const int t1 = token_ids[(row0 + 8) * T_ + tt];

        float cA[4][4], cB[4][4];
        {
            const float* e0 = g_embWp[d][t0] + nc * 128 + w_n * 32;
            const float* e1 = g_embWp[d][t1] + nc * 128 + w_n * 32;
#pragma unroll
            for (int ns = 0; ns < 4; ns++) {
                const int cb = ns * 8 + 2 * l4;
                float2 x0 = *(const float2*)(e0 + cb);
                float2 x1 = *(const float2*)(e1 + cb);
                cA[ns][0] = x0.x; cA[ns][1] = x0.y;
                cA[ns][2] = x1.x; cA[ns][3] = x1.y;
                cB[ns][0] = 0.f; cB[ns][1] = 0.f; cB[ns][2] = 0.f; cB[ns][3] = 0.f;
            }
        }

        if (s > 0) {
            const int par = (s - 1) & 1;
            const unsigned ph = (unsigned)(((s - 1) >> 1) & 1);
            mbar_wait_cluster(barBase + (w_m * 2 + par) * 8, ph);

            const uint4* A_ = sBuf + par * 1024 + w_m * 32 + l;
#pragma unroll
            for (int kc = 0; kc < 16; kc++) {
                uint4 A = A_[kc * 64];       // slot = kc*2 + w_m
                uint4 bv0 = sU[((kc * 4 + w_n) * 2 + 0) * 32 + l];
                uint4 bv1 = sU[((kc * 4 + w_n) * 2 + 1) * 32 + l];
                const unsigned* Ar = (const unsigned*)&A;
                float (*cd)[4] = (kc & 1) ? cB : cA;
                mma16(cd[0], Ar, bv0.x, bv0.y);
                mma16(cd[1], Ar, bv0.z, bv0.w);
                mma16(cd[2], Ar, bv1.x, bv1.y);
                mma16(cd[3], Ar, bv1.z, bv1.w);
            }
        }

        // ---- merge + elementwise + h publish via DSMEM push
        const int parw = s & 1;
        const bool msk = (hi4 ? t1 : t0) != 0;
        unsigned words[4];
#pragma unroll
        for (int ns = 0; ns < 4; ns++) {
            const float z0 = cA[ns][0] + cB[ns][0];
            const float z1 = cA[ns][1] + cB[ns][1];
            const float z2 = cA[ns][2] + cB[ns][2];
            const float z3 = cA[ns][3] + cB[ns][3];
            float s0 = hi4 ? z0 : z2;
            float s1 = hi4 ? z1 : z3;
            float q0 = __shfl_xor_sync(0xffffffffu, s0, 2);
            float q1 = __shfl_xor_sync(0xffffffffu, s1, 2);
            const float zi = hi4 ? q0 : z0;
            const float zf = hi4 ? q1 : z1;
            const float zg = hi4 ? z2 : q0;
            const float zo = hi4 ? z3 : q1;
            const float ii = sigx(zi);
            const float ff = sigx(zf);
            const float gg = tapx(zg);
            const float oo = sigx(zo);
            const float cn = fmaf(ff, cs[ns], ii * gg);
            const float hn = oo * tapx(cn);
            const float cn2 = msk ? cn : cs[ns];
            const float hn2 = msk ? hn : hs[ns];
            cs[ns] = cn2;
            hs[ns] = hn2;
            unsigned hb = (unsigned)__half_as_ushort(__float2half_rn(hn2));
            unsigned pb = __shfl_xor_sync(0xffffffffu, hb, 1);
            // both lanes of the (l, l^1) pair reconstruct the SAME packed word
            words[ns] = ((l4 & 1) == 0) ? ((hb & 0xffffu) | (pb << 16))
                                        : ((pb & 0xffffu) | (hb << 16));
        }

        if (s < T_ - 1) {
            // push the 4 words to this lane's 4 target CTAs (byte offsets within sBuf)
#pragma unroll
            for (int ns = 0; ns < 4; ns++) {
                const unsigned bofs =
                    ((parw * 1024 + (kcP * 2 + w_m) * 32 + ld4 * 4 + ns) * 4 + regP) * 4;
#pragma unroll
                for (int rr = 0; rr < 4; rr++)
                    asm volatile("st.shared::cluster.u32 [%0], %1;"
                                 :: "r"(rbuf[r0 + rr] + bofs), "r"(words[ns]) : "memory");
            }
            // per-thread release-arrive on each target's barrier (orders own stores)
            const unsigned bofsBar = (unsigned)((w_m * 2 + parw) * 8);
#pragma unroll
            for (int rr = 0; rr < 4; rr++)
                asm volatile("mbarrier.arrive.release.cluster.shared::cluster.b64 _, [%0];"
                             :: "r"(rbar[r0 + rr] + bofsBar) : "memory");
        } else {
            // final step: publish h to global for the output projection
            unsigned* hbase = (unsigned*)(g_HA4 + ((d * 2 + 1) * 8 + m) * 1024);
            if ((l4 & 1) == 0) {
#pragma unroll
                for (int ns = 0; ns < 4; ns++)
                    hbase[((kcP * 2 + w_m) * 32 + ld4 * 4 + ns) * 4 + regP] = words[ns];
            }
        }
    }

    asm volatile("barrier.cluster.arrive.aligned;" ::: "memory");
    asm volatile("barrier.cluster.wait.aligned;" ::: "memory");
}

// ---------------- kernel 4: output projection ------------------------------
__global__ void output_kernel(const float* __restrict__ Wout, const float* __restrict__ bout,
                              float* __restrict__ out) {
    const int b = blockIdx.x * blockDim.x + threadIdx.x;
    if (b >= B_) return;
    float a0 = bout[0], a1 = bout[1];
    const int m = b >> 5, row = b & 31;
    const int ms = row >> 4, rlo = row & 15;
#pragma unroll 1
    for (int k = 0; k < H_; k++) {
        const int kc = k >> 4, kj = k & 15, kjl = kj & 7;
        const int lc = (rlo & 7) * 4 + (kjl >> 1);
        const int reg = ((rlo >= 8) ? 1 : 0) + ((kj >= 8) ? 2 : 0);
        const int off = ((kc * 2 + ms) * 32 + lc) * 4 + reg;
        unsigned uf = ((const unsigned*)(g_HA4 + ((0 * 2 + 1) * 8 + m) * 1024))[off];
        unsigned ur = ((const unsigned*)(g_HA4 + ((1 * 2 + 1) * 8 + m) * 1024))[off];
        unsigned sf = (kj & 1) ? (uf >> 16) : (uf & 0xffffu);
        unsigned sr = (kj & 1) ? (ur >> 16) : (ur & 0xffffu);
        const float f  = __half2float(__ushort_as_half((unsigned short)sf));
        const float rr = __half2float(__ushort_as_half((unsigned short)sr));
        a0 += f * Wout[2 * k]     + rr * Wout[2 * (H_ + k)];
        a1 += f * Wout[2 * k + 1] + rr * Wout[2 * (H_ + k) + 1];
    }
    out[2 * b]     = a0;
    out[2 * b + 1] = a1;
}

// ---------------- launch ----------------------------------------------------
extern "C" void kernel_launch(void* const* d_in, const int* in_sizes, int n_in,
                              void* d_out, int out_size) {
    const int*   tok   = (const int*)d_in[0];
    const float* emb   = (const float*)d_in[1];
    const float* W_f   = (const float*)d_in[2];
    const float* U_f   = (const float*)d_in[3];
    const float* b_f   = (const float*)d_in[4];
    const float* W_b   = (const float*)d_in[5];
    const float* U_b   = (const float*)d_in[6];
    const float* b_b   = (const float*)d_in[7];
    const float* W_out = (const float*)d_in[8];
    const float* b_out = (const float*)d_in[9];
    float* out = (float*)d_out;

    const int smem_bytes = (4096 + 2048) * sizeof(uint4);   // 98304
    cudaFuncSetAttribute(lstm_kernel, cudaFuncAttributeMaxDynamicSharedMemorySize, smem_bytes);

    precompute_embW<<<dim3(16, 32, 2), 256>>>(emb, W_f, b_f, W_b, b_b);
    build_Uf16<<<256, 256>>>(U_f, U_b);
    lstm_kernel<<<128, 256, smem_bytes>>>(tok);
    output_kernel<<<1, 256>>>(W_out, b_out, out);
}

// round 8
// speedup vs baseline: 1.6406x; 1.6406x over previous
#include <cuda_runtime.h>
#include <cuda_fp16.h>
#include <cstdint>

#define B_ 256
#define T_ 512
#define D_ 512
#define H_ 256
#define V_ 512

// ---------------- persistent device scratch --------------------------------
__device__ float    g_embWp[2][V_][1024];             // emb@W + b, gate-permuted cols (fp32)
__device__ uint4    g_Uf16[2 * 8 * 16 * 4 * 2 * 32];  // U fp16 b-frags [d][nc][kc16][wn4][p2][lane]
__device__ uint4    g_HA4[2 * 2 * 8 * 1024];          // h fp16 A-frags [d][par][m][kc16][ms2][lane]
__device__ unsigned g_flag[2][8][2][4][4];            // flags [d][m][w_m][src_ncp][w_n]

// ---------------- helpers --------------------------------------------------
__device__ __forceinline__ float tapx(float x) {
    float r; asm("tanh.approx.f32 %0, %1;" : "=f"(r) : "f"(x));
    return r;
}
__device__ __forceinline__ float sigx(float x) { return fmaf(tapx(0.5f * x), 0.5f, 0.5f); }
__device__ __forceinline__ void mma16(float* c, const unsigned* a, unsigned b0, unsigned b1) {
    asm volatile(
        "mma.sync.aligned.m16n8k16.row.col.f32.f16.f16.f32 "
        "{%0,%1,%2,%3}, {%4,%5,%6,%7}, {%8,%9}, {%0,%1,%2,%3};\n"
        : "+f"(c[0]), "+f"(c[1]), "+f"(c[2]), "+f"(c[3])
        : "r"(a[0]), "r"(a[1]), "r"(a[2]), "r"(a[3]), "r"(b0), "r"(b1));
}
// one k16-chunk for one 128-col tile: 2 B LDS.128 + 4 mma into c[0..3]
__device__ __forceinline__ void chunk_mma(float (*c)[4], const uint4* sUt, int kc,
                                          int w_n, int l, uint4 A) {
    uint4 bv0 = sUt[((kc * 4 + w_n) * 2 + 0) * 32 + l];
    uint4 bv1 = sUt[((kc * 4 + w_n) * 2 + 1) * 32 + l];
    const unsigned* Ar = (const unsigned*)&A;
    mma16(c[0], Ar, bv0.x, bv0.y);
    mma16(c[1], Ar, bv0.z, bv0.w);
    mma16(c[2], Ar, bv1.x, bv1.y);
    mma16(c[3], Ar, bv1.z, bv1.w);
}
__host__ __device__ __forceinline__ int perm_col(int gate, int j) {
    return (j >> 5) * 128 + ((j >> 3) & 3) * 32 + ((j >> 1) & 3) * 8
         + (gate >> 1) * 4 + (j & 1) * 2 + (gate & 1);
}

// ---------------- kernel 0: zero flags --------------------------------------
__global__ void zero_cnt_kernel() {
    int t = blockIdx.x * blockDim.x + threadIdx.x;
    if (t < 2 * 8 * 2 * 4 * 4) ((unsigned*)g_flag)[t] = 0;
}

// ---------------- kernel 1: embW precompute (permuted cols, fp32) ----------
__global__ void precompute_embW(const float* __restrict__ emb,
                                const float* __restrict__ W_f, const float* __restrict__ b_f,
                                const float* __restrict__ W_b, const float* __restrict__ b_b) {
    const int d = blockIdx.z;
    const float* W  = d ? W_b : W_f;
    const float* bv = d ? b_b : b_f;
    const int oc = blockIdx.x * 64 + (threadIdx.x & 63);
    const int v0 = blockIdx.y * 16;
    __shared__ float sE[16 * 512];
    for (int i = threadIdx.x; i < 16 * 512; i += 256) sE[i] = emb[v0 * 512 + i];
    __syncthreads();
    const int vq = threadIdx.x >> 6;
    float acc[4] = {0.f, 0.f, 0.f, 0.f};
    for (int k = 0; k < 512; k++) {
        float wv = W[k * 1024 + oc];
#pragma unroll
        for (int i = 0; i < 4; i++) acc[i] += sE[(vq * 4 + i) * 512 + k] * wv;
    }
    const int gate = oc >> 8, j = oc & 255;
    const int pcol = perm_col(gate, j);
    const float bb = bv[oc];
#pragma unroll
    for (int i = 0; i < 4; i++)
        g_embWp[d][v0 + vq * 4 + i][pcol] = acc[i] + bb;
}

// ---------------- kernel 2: U -> fp16 b-frag layout ------------------------
__global__ void build_Uf16(const float* __restrict__ U_f, const float* __restrict__ U_b) {
    int t = blockIdx.x * blockDim.x + threadIdx.x;
    if (t >= 65536) return;
    const int lane = t & 31;
    const int p    = (t >> 5) & 1;
    const int w    = (t >> 6) & 3;
    const int kc   = (t >> 8) & 15;
    const int nc   = (t >> 12) & 7;
    const int d    = (t >> 15) & 1;
    const float* U = d ? U_b : U_f;
    const int l4 = lane & 3, ld4 = lane >> 2;
    const int o8 = ld4;
    const int gate = (o8 & 1) + 2 * (o8 >> 2);
    const int uSel = (o8 >> 1) & 1;
    unsigned vals[4];
#pragma unroll
    for (int i = 0; i < 4; i++) {
        const int ns = 2 * p + (i >> 1);
        const int k0 = kc * 16 + l4 * 2 + (i & 1) * 8;
        const int j  = nc * 32 + w * 8 + ns * 2 + uSel;
        const int col = gate * 256 + j;
        unsigned h0 = (unsigned)__half_as_ushort(__float2half_rn(U[k0 * 1024 + col]));
        unsigned h1 = (unsigned)__half_as_ushort(__float2half_rn(U[(k0 + 1) * 1024 + col]));
        vals[i] = h0 | (h1 << 16);
    }
    g_Uf16[t] = make_uint4(vals[0], vals[1], vals[2], vals[3]);
}

// ---------------- kernel 3: persistent recurrence (4-CTA groups) -----------
// grid = 64: d(2) x m(8) x ncp(4). Each CTA owns 256 gate cols (2 tiles of 128).
// block = 256 = 8 warps (w_m 2 x w_n 4). Exchange via L2 + flags, self via smem.
__global__ void __launch_bounds__(256, 1)
lstm_kernel(const int* __restrict__ token_ids) {
    extern __shared__ uint4 smem4[];
    uint4* sU0 = smem4;            // 4096 uint4 = 64KB: tile 0 b-frags
    uint4* sU1 = smem4 + 4096;     // 4096 uint4 = 64KB: tile 1 b-frags
    uint4* sSelf4 = smem4 + 8192;  //  512 uint4 =  8KB: [par2][slot8][lane32]
    unsigned* sSelfW = (unsigned*)sSelf4;

    const int tid = threadIdx.x;
    const int bx  = blockIdx.x;
    const int d   = bx >> 5;
    const int m   = (bx >> 2) & 7;
    const int ncp = bx & 3;
    const int wid = tid >> 5;
    const int w_n = wid & 3;
    const int w_m = wid >> 2;
    const int l   = tid & 31;
    const int l4  = l & 3, ld4 = l >> 2;
    const bool hi4 = (l4 >= 2);

    {   // load both U tile slices
        const uint4* s0 = &g_Uf16[(d * 8 + ncp * 2 + 0) * 4096];
        const uint4* s1 = &g_Uf16[(d * 8 + ncp * 2 + 1) * 4096];
        for (int i = tid; i < 4096; i += 256) { sU0[i] = s0[i]; sU1[i] = s1[i]; }
    }
    __syncthreads();

    float cs0[4], hs0[4], cs1[4], hs1[4];
#pragma unroll
    for (int a = 0; a < 4; a++) { cs0[a] = 0.f; hs0[a] = 0.f; cs1[a] = 0.f; hs1[a] = 0.f; }

    const int rbase = m * 32;
    const unsigned* myflags = &g_flag[d][m][w_m][0][0];
    unsigned* myslot = &g_flag[d][m][w_m][ncp][w_n];
    // produced k-chunks (global kc 0..15): tile t -> ncp*4 + t*2 + (w_n>>1)
    const int kcP0 = ncp * 4 + 0 * 2 + (w_n >> 1);
    const int kcP1 = ncp * 4 + 1 * 2 + (w_n >> 1);
    const int kcL0 = 0 * 2 + (w_n >> 1);        // local mirror slots 0..3
    const int kcL1 = 1 * 2 + (w_n >> 1);
    const int regP = (hi4 ? 1 : 0) + ((w_n & 1) ? 2 : 0);

    for (int s = 0; s < T_; s++) {
        const int tt = d ? (T_ - 1 - s) : s;

        const int row0 = rbase + w_m * 16 + ld4;
        const int t0 = token_ids[row0 * T_ + tt];
        const int t1 = token_ids[(row0 + 8) * T_ + tt];

        float c0[4][4], c1[4][4];
        {
            const float* ea0 = g_embWp[d][t0] + ncp * 256 + w_n * 32;          // tile0 row t0
            const float* eb0 = g_embWp[d][t1] + ncp * 256 + w_n * 32;          // tile0 row t1
            const float* ea1 = ea0 + 128;                                       // tile1
            const float* eb1 = eb0 + 128;
#pragma unroll
            for (int ns = 0; ns < 4; ns++) {
                const int cb = ns * 8 + 2 * l4;
                float2 x0 = *(const float2*)(ea0 + cb);
                float2 x1 = *(const float2*)(eb0 + cb);
                float2 x2 = *(const float2*)(ea1 + cb);
                float2 x3 = *(const float2*)(eb1 + cb);
                c0[ns][0] = x0.x; c0[ns][1] = x0.y;
                c0[ns][2] = x1.x; c0[ns][3] = x1.y;
                c1[ns][0] = x2.x; c1[ns][1] = x2.y;
                c1[ns][2] = x3.x; c1[ns][3] = x3.y;
            }
        }

        if (s > 0) {
            const unsigned tgt = (unsigned)s;
            const int par = (s - 1) & 1;
            const uint4* gsrc = g_HA4 + ((d * 2 + par) * 8 + m) * 1024;

            // ---- self chunks from local smem mirror (4 chunks)
            {
#pragma unroll
                for (int q = 0; q < 4; q++) {
                    uint4 A = sSelf4[par * 256 + (q * 2 + w_m) * 32 + l];
                    const int kcg = ncp * 4 + q;
                    chunk_mma(c0, sU0, kcg, w_n, l, A);
                    chunk_mma(c1, sU1, kcg, w_n, l, A);
                }
            }

            // ---- 3 remote sources, processed in arrival order
            unsigned pend = 0xFu & ~(1u << ncp);
            while (pend) {
                unsigned avail = 0;
                do {
                    unsigned v;
                    const unsigned* fp = myflags + (l & 15);
                    asm volatile("ld.acquire.gpu.global.b32 %0, [%1];"
                                 : "=r"(v) : "l"(fp) : "memory");
                    unsigned rdy = __ballot_sync(0xffffffffu, (l >= 16) || v >= tgt);
                    unsigned x = rdy & (rdy >> 1) & (rdy >> 2) & (rdy >> 3);
                    unsigned m4 = (x & 1u) | ((x >> 3) & 2u) | ((x >> 6) & 4u) | ((x >> 9) & 8u);
                    avail = m4 & pend;
                } while (!avail);
                pend &= ~avail;

                while (avail) {
                    const int j0 = __ffs(avail) - 1; avail &= avail - 1;
                    int j1 = -1;
                    if (avail) { j1 = __ffs(avail) - 1; avail &= avail - 1; }
                    uint4 a0, a1, a2, a3, b0, b1, b2, b3;
                    a0 = __ldcg(gsrc + ((j0 * 4 + 0) * 2 + w_m) * 32 + l);
                    a1 = __ldcg(gsrc + ((j0 * 4 + 1) * 2 + w_m) * 32 + l);
                    a2 = __ldcg(gsrc + ((j0 * 4 + 2) * 2 + w_m) * 32 + l);
                    a3 = __ldcg(gsrc + ((j0 * 4 + 3) * 2 + w_m) * 32 + l);
                    if (j1 >= 0) {
                        b0 = __ldcg(gsrc + ((j1 * 4 + 0) * 2 + w_m) * 32 + l);
                        b1 = __ldcg(gsrc + ((j1 * 4 + 1) * 2 + w_m) * 32 + l);
                        b2 = __ldcg(gsrc + ((j1 * 4 + 2) * 2 + w_m) * 32 + l);
                        b3 = __ldcg(gsrc + ((j1 * 4 + 3) * 2 + w_m) * 32 + l);
                    }
                    chunk_mma(c0, sU0, j0 * 4 + 0, w_n, l, a0);
                    chunk_mma(c1, sU1, j0 * 4 + 0, w_n, l, a0);
                    chunk_mma(c0, sU0, j0 * 4 + 1, w_n, l, a1);
                    chunk_mma(c1, sU1, j0 * 4 + 1, w_n, l, a1);
                    chunk_mma(c0, sU0, j0 * 4 + 2, w_n, l, a2);
                    chunk_mma(c1, sU1, j0 * 4 + 2, w_n, l, a2);
                    chunk_mma(c0, sU0, j0 * 4 + 3, w_n, l, a3);
                    chunk_mma(c1, sU1, j0 * 4 + 3, w_n, l, a3);
                    if (j1 >= 0) {
                        chunk_mma(c0, sU0, j1 * 4 + 0, w_n, l, b0);
                        chunk_mma(c1, sU1, j1 * 4 + 0, w_n, l, b0);
                        chunk_mma(c0, sU0, j1 * 4 + 1, w_n, l, b1);
                        chunk_mma(c1, sU1, j1 * 4 + 1, w_n, l, b1);
                        chunk_mma(c0, sU0, j1 * 4 + 2, w_n, l, b2);
                        chunk_mma(c1, sU1, j1 * 4 + 2, w_n, l, b2);
                        chunk_mma(c0, sU0, j1 * 4 + 3, w_n, l, b3);
                        chunk_mma(c1, sU1, j1 * 4 + 3, w_n, l, b3);
                    }
                }
            }
        }

        // ---- elementwise per tile + publish (global + smem mirror)
        unsigned* hbase = (unsigned*)(g_HA4 + ((d * 2 + (s & 1)) * 8 + m) * 1024);
        const int parw = (s & 1) * 1024;
        const bool msk = (hi4 ? t1 : t0) != 0;
#pragma unroll
        for (int t = 0; t < 2; t++) {
            float (*c_)[4] = t ? c1 : c0;
            float* cs = t ? cs1 : cs0;
            float* hs = t ? hs1 : hs0;
            const int kcP = t ? kcP1 : kcP0;
            const int kcL = t ? kcL1 : kcL0;
#pragma unroll
            for (int ns = 0; ns < 4; ns++) {
                float s0 = hi4 ? c_[ns][0] : c_[ns][2];
                float s1 = hi4 ? c_[ns][1] : c_[ns][3];
                float q0 = __shfl_xor_sync(0xffffffffu, s0, 2);
                float q1 = __shfl_xor_sync(0xffffffffu, s1, 2);
                const float zi = hi4 ? q0 : c_[ns][0];
                const float zf = hi4 ? q1 : c_[ns][1];
                const float zg = hi4 ? c_[ns][2] : q0;
                const float zo = hi4 ? c_[ns][3] : q1;
                const float ii = sigx(zi);
                const float ff = sigx(zf);
                const float gg = tapx(zg);
                const float oo = sigx(zo);
                const float cn = fmaf(ff, cs[ns], ii * gg);
                const float hn = oo * tapx(cn);
                const float cn2 = msk ? cn : cs[ns];
                const float hn2 = msk ? hn : hs[ns];
                cs[ns] = cn2;
                hs[ns] = hn2;
                unsigned hb = (unsigned)__half_as_ushort(__float2half_rn(hn2));
                unsigned pb = __shfl_xor_sync(0xffffffffu, hb, 1);
                if ((l4 & 1) == 0) {
                    unsigned word = (hb & 0xffffu) | (pb << 16);
                    hbase[((kcP * 2 + w_m) * 32 + ld4 * 4 + ns) * 4 + regP] = word;
                    sSelfW[parw + ((kcL * 2 + w_m) * 32 + ld4 * 4 + ns) * 4 + regP] = word;
                }
            }
        }
        __syncwarp();
        if (l == 0)
            asm volatile("st.release.gpu.global.b32 [%0], %1;"
                         :: "l"(myslot), "r"((unsigned)(s + 1)) : "memory");
        // intra-group barrier: mirror visibility + parity reuse protection
        asm volatile("bar.sync %0, %1;" :: "r"(1 + w_m), "r"(128) : "memory");
    }
}

// ---------------- kernel 4: output projection ------------------------------
__global__ void output_kernel(const float* __restrict__ Wout, const float* __restrict__ bout,
                              float* __restrict__ out) {
    const int b = blockIdx.x * blockDim.x + threadIdx.x;
    if (b >= B_) return;
    float a0 = bout[0], a1 = bout[1];
    const int m = b >> 5, row = b & 31;
    const int ms = row >> 4, rlo = row & 15;
#pragma unroll 1
    for (int k = 0; k < H_; k++) {
        const int kc = k >> 4, kj = k & 15, kjl = kj & 7;
        const int lc = (rlo & 7) * 4 + (kjl >> 1);
        const int reg = ((rlo >= 8) ? 1 : 0) + ((kj >= 8) ? 2 : 0);
        const int off = ((kc * 2 + ms) * 32 + lc) * 4 + reg;
        unsigned uf = ((const unsigned*)(g_HA4 + ((0 * 2 + 1) * 8 + m) * 1024))[off];
        unsigned ur = ((const unsigned*)(g_HA4 + ((1 * 2 + 1) * 8 + m) * 1024))[off];
        unsigned sf = (kj & 1) ? (uf >> 16) : (uf & 0xffffu);
        unsigned sr = (kj & 1) ? (ur >> 16) : (ur & 0xffffu);
        const float f  = __half2float(__ushort_as_half((unsigned short)sf));
        const float rr = __half2float(__ushort_as_half((unsigned short)sr));
        a0 += f * Wout[2 * k]     + rr * Wout[2 * (H_ + k)];
        a1 += f * Wout[2 * k + 1] + rr * Wout[2 * (H_ + k) + 1];
    }
    out[2 * b]     = a0;
    out[2 * b + 1] = a1;
}

// ---------------- launch ----------------------------------------------------
extern "C" void kernel_launch(void* const* d_in, const int* in_sizes, int n_in,
                              void* d_out, int out_size) {
    const int*   tok   = (const int*)d_in[0];
    const float* emb   = (const float*)d_in[1];
    const float* W_f   = (const float*)d_in[2];
    const float* U_f   = (const float*)d_in[3];
    const float* b_f   = (const float*)d_in[4];
    const float* W_b   = (const float*)d_in[5];
    const float* U_b   = (const float*)d_in[6];
    const float* b_b   = (const float*)d_in[7];
    const float* W_out = (const float*)d_in[8];
    const float* b_out = (const float*)d_in[9];
    float* out = (float*)d_out;

    const int smem_bytes = (8192 + 512) * sizeof(uint4);   // 139264
    cudaFuncSetAttribute(lstm_kernel, cudaFuncAttributeMaxDynamicSharedMemorySize, smem_bytes);

    zero_cnt_kernel<<<2, 256>>>();
    precompute_embW<<<dim3(16, 32, 2), 256>>>(emb, W_f, b_f, W_b, b_b);
    build_Uf16<<<256, 256>>>(U_f, U_b);
    lstm_kernel<<<64, 256, smem_bytes>>>(tok);
    output_kernel<<<1, 256>>>(W_out, b_out, out);
}

// round 9
// speedup vs baseline: 2.3149x; 1.4110x over previous
#include <cuda_runtime.h>
#include <cuda_fp16.h>
#include <cstdint>

#define B_ 256
#define T_ 512
#define D_ 512
#define H_ 256
#define V_ 512

// ---------------- persistent device scratch --------------------------------
__device__ float    g_embWp[2][V_][1024];             // emb@W + b, gate-permuted cols (fp32)
__device__ uint4    g_Uf16[2 * 8 * 16 * 4 * 2 * 32];  // U fp16 b-frags [d][nc][kc16][wn4][p2][lane]
__device__ uint4    g_HA4[2 * 2 * 16 * 512];          // h fp16 A-frags [d][par][mg][kc16][lane]
__device__ unsigned g_flag[2][16][4][8];              // flags [d][mg][src_ncp][wid]

// ---------------- helpers --------------------------------------------------
__device__ __forceinline__ float tapx(float x) {
    float r; asm("tanh.approx.f32 %0, %1;" : "=f"(r) : "f"(x));
    return r;
}
__device__ __forceinline__ float sigx(float x) { return fmaf(tapx(0.5f * x), 0.5f, 0.5f); }
__device__ __forceinline__ void mma16(float* c, const unsigned* a, unsigned b0, unsigned b1) {
    asm volatile(
        "mma.sync.aligned.m16n8k16.row.col.f32.f16.f16.f32 "
        "{%0,%1,%2,%3}, {%4,%5,%6,%7}, {%8,%9}, {%0,%1,%2,%3};\n"
        : "+f"(c[0]), "+f"(c[1]), "+f"(c[2]), "+f"(c[3])
        : "r"(a[0]), "r"(a[1]), "r"(a[2]), "r"(a[3]), "r"(b0), "r"(b1));
}
// one k16-chunk: 2 B LDS.128 + 4 mma into c[0..3]
__device__ __forceinline__ void chunk_mma(float (*c)[4], const uint4* sUt, int kc,
                                          int w_nl, int l, uint4 A) {
    uint4 bv0 = sUt[((kc * 4 + w_nl) * 2 + 0) * 32 + l];
    uint4 bv1 = sUt[((kc * 4 + w_nl) * 2 + 1) * 32 + l];
    const unsigned* Ar = (const unsigned*)&A;
    mma16(c[0], Ar, bv0.x, bv0.y);
    mma16(c[1], Ar, bv0.z, bv0.w);
    mma16(c[2], Ar, bv1.x, bv1.y);
    mma16(c[3], Ar, bv1.z, bv1.w);
}
__host__ __device__ __forceinline__ int perm_col(int gate, int j) {
    return (j >> 5) * 128 + ((j >> 3) & 3) * 32 + ((j >> 1) & 3) * 8
         + (gate >> 1) * 4 + (j & 1) * 2 + (gate & 1);
}

// ---------------- kernel 0: zero flags --------------------------------------
__global__ void zero_cnt_kernel() {
    int t = blockIdx.x * blockDim.x + threadIdx.x;
    if (t < 2 * 16 * 4 * 8) ((unsigned*)g_flag)[t] = 0;
}

// ---------------- kernel 1: embW precompute (permuted cols, fp32) ----------
__global__ void precompute_embW(const float* __restrict__ emb,
                                const float* __restrict__ W_f, const float* __restrict__ b_f,
                                const float* __restrict__ W_b, const float* __restrict__ b_b) {
    const int d = blockIdx.z;
    const float* W  = d ? W_b : W_f;
    const float* bv = d ? b_b : b_f;
    const int oc = blockIdx.x * 64 + (threadIdx.x & 63);
    const int v0 = blockIdx.y * 16;
    __shared__ float sE[16 * 512];
    for (int i = threadIdx.x; i < 16 * 512; i += 256) sE[i] = emb[v0 * 512 + i];
    __syncthreads();
    const int vq = threadIdx.x >> 6;
    float acc[4] = {0.f, 0.f, 0.f, 0.f};
    for (int k = 0; k < 512; k++) {
        float wv = W[k * 1024 + oc];
#pragma unroll
        for (int i = 0; i < 4; i++) acc[i] += sE[(vq * 4 + i) * 512 + k] * wv;
    }
    const int gate = oc >> 8, j = oc & 255;
    const int pcol = perm_col(gate, j);
    const float bb = bv[oc];
#pragma unroll
    for (int i = 0; i < 4; i++)
        g_embWp[d][v0 + vq * 4 + i][pcol] = acc[i] + bb;
}

// ---------------- kernel 2: U -> fp16 b-frag layout ------------------------
__global__ void build_Uf16(const float* __restrict__ U_f, const float* __restrict__ U_b) {
    int t = blockIdx.x * blockDim.x + threadIdx.x;
    if (t >= 65536) return;
    const int lane = t & 31;
    const int p    = (t >> 5) & 1;
    const int w    = (t >> 6) & 3;
    const int kc   = (t >> 8) & 15;
    const int nc   = (t >> 12) & 7;
    const int d    = (t >> 15) & 1;
    const float* U = d ? U_b : U_f;
    const int l4 = lane & 3, ld4 = lane >> 2;
    const int o8 = ld4;
    const int gate = (o8 & 1) + 2 * (o8 >> 2);
    const int uSel = (o8 >> 1) & 1;
    unsigned vals[4];
#pragma unroll
    for (int i = 0; i < 4; i++) {
        const int ns = 2 * p + (i >> 1);
        const int k0 = kc * 16 + l4 * 2 + (i & 1) * 8;
        const int j  = nc * 32 + w * 8 + ns * 2 + uSel;
        const int col = gate * 256 + j;
        unsigned h0 = (unsigned)__half_as_ushort(__float2half_rn(U[k0 * 1024 + col]));
        unsigned h1 = (unsigned)__half_as_ushort(__float2half_rn(U[(k0 + 1) * 1024 + col]));
        vals[i] = h0 | (h1 << 16);
    }
    g_Uf16[t] = make_uint4(vals[0], vals[1], vals[2], vals[3]);
}

// ---------------- kernel 3: persistent recurrence (rows 16 / CTA) ----------
// grid = 128: d(2) x mg(16: 16 rows) x ncp(4: 256 gate cols).
// block = 256 = 8 warps; warp wid owns cols ncp*256 + wid*32 (R6-size tile).
__global__ void __launch_bounds__(256, 1)
lstm_kernel(const int* __restrict__ token_ids) {
    extern __shared__ uint4 smem4[];
    uint4* sU0 = smem4;            // 4096 uint4 = 64KB: cols 0..127 b-frags
    uint4* sU1 = smem4 + 4096;     // 4096 uint4 = 64KB: cols 128..255 b-frags
    uint4* sSelf4 = smem4 + 8192;  //  256 uint4 =  4KB: [par2][kc4][lane32]
    unsigned* sSelfW = (unsigned*)sSelf4;

    const int tid = threadIdx.x;
    const int bx  = blockIdx.x;
    const int d   = bx >> 6;
    const int mg  = (bx >> 2) & 15;
    const int ncp = bx & 3;
    const int wid = tid >> 5;
    const int w_nl = wid & 3;
    const int l   = tid & 31;
    const int l4  = l & 3, ld4 = l >> 2;
    const bool hi4 = (l4 >= 2);
    const uint4* sUt = (wid >= 4) ? sU1 : sU0;

    {   // load both U tile slices (128KB)
        const uint4* s0 = &g_Uf16[(d * 8 + ncp * 2 + 0) * 4096];
        const uint4* s1 = &g_Uf16[(d * 8 + ncp * 2 + 1) * 4096];
        for (int i = tid; i < 4096; i += 256) { sU0[i] = s0[i]; sU1[i] = s1[i]; }
    }
    __syncthreads();

    float cs[4], hs[4];
#pragma unroll
    for (int a = 0; a < 4; a++) { cs[a] = 0.f; hs[a] = 0.f; }

    const int rbase = mg * 16;
    const unsigned* myflags = &g_flag[d][mg][0][0];
    unsigned* myslot = &g_flag[d][mg][ncp][wid];
    const int kcP = ncp * 4 + (wid >> 1);     // produced k-chunk (global)
    const int kcL = wid >> 1;                 // local mirror slot
    const int regP = (hi4 ? 1 : 0) + ((wid & 1) ? 2 : 0);

    for (int s = 0; s < T_; s++) {
        const int tt = d ? (T_ - 1 - s) : s;

        const int t0 = token_ids[(rbase + ld4) * T_ + tt];
        const int t1 = token_ids[(rbase + ld4 + 8) * T_ + tt];

        float c_[4][4];
        {
            const float* ea = g_embWp[d][t0] + ncp * 256 + wid * 32;
            const float* eb = g_embWp[d][t1] + ncp * 256 + wid * 32;
#pragma unroll
            for (int ns = 0; ns < 4; ns++) {
                const int cb = ns * 8 + 2 * l4;
                float2 x0 = *(const float2*)(ea + cb);
                float2 x1 = *(const float2*)(eb + cb);
                c_[ns][0] = x0.x; c_[ns][1] = x0.y;
                c_[ns][2] = x1.x; c_[ns][3] = x1.y;
            }
        }

        if (s > 0) {
            const unsigned tgt = (unsigned)s;
            const int par = (s - 1) & 1;
            const uint4* gsrc = g_HA4 + ((d * 2 + par) * 16 + mg) * 512;

            // ---- self chunks from local smem mirror (4 chunks)
#pragma unroll
            for (int q = 0; q < 4; q++) {
                uint4 A = sSelf4[par * 128 + q * 32 + l];
                chunk_mma(c_, sUt, ncp * 4 + q, w_nl, l, A);
            }

            // ---- 3 remote sources, processed in arrival order
            unsigned pend = 0xFu & ~(1u << ncp);
            while (pend) {
                unsigned avail = 0;
                do {
                    unsigned v;
                    asm volatile("ld.acquire.gpu.global.b32 %0, [%1];"
                                 : "=r"(v) : "l"(myflags + l) : "memory");
                    unsigned rdy = __ballot_sync(0xffffffffu, v >= tgt);
                    unsigned x = rdy & (rdy >> 1) & (rdy >> 2) & (rdy >> 3)
                               & (rdy >> 4) & (rdy >> 5) & (rdy >> 6) & (rdy >> 7);
                    unsigned m4 = (x & 1u) | ((x >> 7) & 2u) | ((x >> 14) & 4u) | ((x >> 21) & 8u);
                    avail = m4 & pend;
                } while (!avail);
                pend &= ~avail;

                while (avail) {
                    const int j = __ffs(avail) - 1; avail &= avail - 1;
                    uint4 a0 = __ldcg(gsrc + (j * 4 + 0) * 32 + l);
                    uint4 a1 = __ldcg(gsrc + (j * 4 + 1) * 32 + l);
                    uint4 a2 = __ldcg(gsrc + (j * 4 + 2) * 32 + l);
                    uint4 a3 = __ldcg(gsrc + (j * 4 + 3) * 32 + l);
                    chunk_mma(c_, sUt, j * 4 + 0, w_nl, l, a0);
                    chunk_mma(c_, sUt, j * 4 + 1, w_nl, l, a1);
                    chunk_mma(c_, sUt, j * 4 + 2, w_nl, l, a2);
                    chunk_mma(c_, sUt, j * 4 + 3, w_nl, l, a3);
                }
            }
        }

        // ---- elementwise (register state) + fp16 pack + publish
        unsigned* hbase = (unsigned*)(g_HA4 + ((d * 2 + (s & 1)) * 16 + mg) * 512);
        const int parw = (s & 1) * 512;
        const bool msk = (hi4 ? t1 : t0) != 0;
#pragma unroll
        for (int ns = 0; ns < 4; ns++) {
            float s0 = hi4 ? c_[ns][0] : c_[ns][2];
            float s1 = hi4 ? c_[ns][1] : c_[ns][3];
            float q0 = __shfl_xor_sync(0xffffffffu, s0, 2);
            float q1 = __shfl_xor_sync(0xffffffffu, s1, 2);
            const float zi = hi4 ? q0 : c_[ns][0];
            const float zf = hi4 ? q1 : c_[ns][1];
            const float zg = hi4 ? c_[ns][2] : q0;
            const float zo = hi4 ? c_[ns][3] : q1;
            const float ii = sigx(zi);
            const float ff = sigx(zf);
            const float gg = tapx(zg);
            const float oo = sigx(zo);
            const float cn = fmaf(ff, cs[ns], ii * gg);
            const float hn = oo * tapx(cn);
            const float cn2 = msk ? cn : cs[ns];
            const float hn2 = msk ? hn : hs[ns];
            cs[ns] = cn2;
            hs[ns] = hn2;
            unsigned hb = (unsigned)__half_as_ushort(__float2half_rn(hn2));
            unsigned pb = __shfl_xor_sync(0xffffffffu, hb, 1);
            if ((l4 & 1) == 0) {
                unsigned word = (hb & 0xffffu) | (pb << 16);
                hbase[(kcP * 32 + ld4 * 4 + ns) * 4 + regP] = word;
                sSelfW[parw + (kcL * 32 + ld4 * 4 + ns) * 4 + regP] = word;
            }
        }
        __syncwarp();
        if (l == 0)
            asm volatile("st.release.gpu.global.b32 [%0], %1;"
                         :: "l"(myslot), "r"((unsigned)(s + 1)) : "memory");
        __syncthreads();   // mirror visibility + parity reuse protection
    }
}

// ---------------- kernel 4: output projection (1 warp / batch row) ---------
__global__ void output_kernel(const float* __restrict__ Wout, const float* __restrict__ bout,
                              float* __restrict__ out) {
    const int b = blockIdx.x;
    const int l = threadIdx.x;
    const int mg = b >> 4, r = b & 15;
    const unsigned* hf = (const unsigned*)(g_HA4 + ((0 * 2 + 1) * 16 + mg) * 512);
    const unsigned* hr = (const unsigned*)(g_HA4 + ((1 * 2 + 1) * 16 + mg) * 512);
    float a0 = 0.f, a1 = 0.f;
#pragma unroll
    for (int i = 0; i < 8; i++) {
        const int k = l * 8 + i;
        const int kc = k >> 4, kj = k & 15;
        const int lc = (r & 7) * 4 + ((kj & 7) >> 1);
        const int reg = ((r >= 8) ? 1 : 0) + ((kj >= 8) ? 2 : 0);
        const int off = (kc * 32 + lc) * 4 + reg;
        unsigned uf = hf[off], ur = hr[off];
        unsigned sf = (kj & 1) ? (uf >> 16) : (uf & 0xffffu);
        unsigned sr = (kj & 1) ? (ur >> 16) : (ur & 0xffffu);
        const float f  = __half2float(__ushort_as_half((unsigned short)sf));
        const float rr = __half2float(__ushort_as_half((unsigned short)sr));
        a0 += f * Wout[2 * k]     + rr * Wout[2 * (H_ + k)];
        a1 += f * Wout[2 * k + 1] + rr * Wout[2 * (H_ + k) + 1];
    }
#pragma unroll
    for (int o = 16; o; o >>= 1) {
        a0 += __shfl_down_sync(0xffffffffu, a0, o);
        a1 += __shfl_down_sync(0xffffffffu, a1, o);
    }
    if (l == 0) {
        out[2 * b]     = a0 + bout[0];
        out[2 * b + 1] = a1 + bout[1];
    }
}

// ---------------- launch ----------------------------------------------------
extern "C" void kernel_launch(void* const* d_in, const int* in_sizes, int n_in,
                              void* d_out, int out_size) {
    const int*   tok   = (const int*)d_in[0];
    const float* emb   = (const float*)d_in[1];
    const float* W_f   = (const float*)d_in[2];
    const float* U_f   = (const float*)d_in[3];
    const float* b_f   = (const float*)d_in[4];
    const float* W_b   = (const float*)d_in[5];
    const float* U_b   = (const float*)d_in[6];
    const float* b_b   = (const float*)d_in[7];
    const float* W_out = (const float*)d_in[8];
    const float* b_out = (const float*)d_in[9];
    float* out = (float*)d_out;

    const int smem_bytes = (8192 + 256) * sizeof(uint4);   // 135168
    cudaFuncSetAttribute(lstm_kernel, cudaFuncAttributeMaxDynamicSharedMemorySize, smem_bytes);

    zero_cnt_kernel<<<4, 256>>>();
    precompute_embW<<<dim3(16, 32, 2), 256>>>(emb, W_f, b_f, W_b, b_b);
    build_Uf16<<<256, 256>>>(U_f, U_b);
    lstm_kernel<<<128, 256, smem_bytes>>>(tok);
    output_kernel<<<B_, 32>>>(W_out, b_out, out);
}

// round 11
// speedup vs baseline: 2.4409x; 1.0544x over previous
#include <cuda_runtime.h>
#include <cuda_fp16.h>
#include <cstdint>

#define B_ 256
#define T_ 512
#define D_ 512
#define H_ 256
#define V_ 512

// ---------------- persistent device scratch --------------------------------
__device__ float    g_embWp[2][V_][1024];             // emb@W + b, gate-permuted cols (fp32)
__device__ uint4    g_Uf16[2 * 8 * 16 * 4 * 2 * 32];  // U fp16 b-frags [d][nc][kc16][wn4][p2][lane]
__device__ uint4    g_HA4[2 * 2 * 16 * 512];          // h fp16 A-frags [d][par][mg][kc16][lane]

// ---------------- helpers --------------------------------------------------
__device__ __forceinline__ float tapx(float x) {
    float r; asm("tanh.approx.f32 %0, %1;" : "=f"(r) : "f"(x));
    return r;
}
__device__ __forceinline__ float sigx(float x) { return fmaf(tapx(0.5f * x), 0.5f, 0.5f); }
__device__ __forceinline__ void mma16(float* c, const unsigned* a, unsigned b0, unsigned b1) {
    asm volatile(
        "mma.sync.aligned.m16n8k16.row.col.f32.f16.f16.f32 "
        "{%0,%1,%2,%3}, {%4,%5,%6,%7}, {%8,%9}, {%0,%1,%2,%3};\n"
        : "+f"(c[0]), "+f"(c[1]), "+f"(c[2]), "+f"(c[3])
        : "r"(a[0]), "r"(a[1]), "r"(a[2]), "r"(a[3]), "r"(b0), "r"(b1));
}
__device__ __forceinline__ uint32_t smem_u32(const void* p) {
    uint32_t a;
    asm("{ .reg .u64 t; cvta.to.shared.u64 t, %1; cvt.u32.u64 %0, t; }" : "=r"(a) : "l"(p));
    return a;
}
__device__ __forceinline__ void mbar_wait_cluster(uint32_t bar, unsigned ph) {
    unsigned done;
    do {
        asm volatile(
            "{ .reg .pred p;\n"
            "  mbarrier.try_wait.parity.acquire.cluster.shared::cta.b64 p, [%1], %2, 0x989680;\n"
            "  selp.b32 %0, 1, 0, p; }"
            : "=r"(done) : "r"(bar), "r"(ph) : "memory");
    } while (!done);
}
__host__ __device__ __forceinline__ int perm_col(int gate, int j) {
    return (j >> 5) * 128 + ((j >> 3) & 3) * 32 + ((j >> 1) & 3) * 8
         + (gate >> 1) * 4 + (j & 1) * 2 + (gate & 1);
}

// ---------------- kernel 1: embW precompute (permuted cols, fp32) ----------
__global__ void precompute_embW(const float* __restrict__ emb,
                                const float* __restrict__ W_f, const float* __restrict__ b_f,
                                const float* __restrict__ W_b, const float* __restrict__ b_b) {
    const int d = blockIdx.z;
    const float* W  = d ? W_b : W_f;
    const float* bv = d ? b_b : b_f;
    const int oc = blockIdx.x * 64 + (threadIdx.x & 63);
    const int v0 = blockIdx.y * 16;
    __shared__ float sE[16 * 512];
    for (int i = threadIdx.x; i < 16 * 512; i += 256) sE[i] = emb[v0 * 512 + i];
    __syncthreads();
    const int vq = threadIdx.x >> 6;
    float acc[4] = {0.f, 0.f, 0.f, 0.f};
    for (int k = 0; k < 512; k++) {
        float wv = W[k * 1024 + oc];
#pragma unroll
        for (int i = 0; i < 4; i++) acc[i] += sE[(vq * 4 + i) * 512 + k] * wv;
    }
    const int gate = oc >> 8, j = oc & 255;
    const int pcol = perm_col(gate, j);
    const float bb = bv[oc];
#pragma unroll
    for (int i = 0; i < 4; i++)
        g_embWp[d][v0 + vq * 4 + i][pcol] = acc[i] + bb;
}

// ---------------- kernel 2: U -> fp16 b-frag layout ------------------------
__global__ void build_Uf16(const float* __restrict__ U_f, const float* __restrict__ U_b) {
    int t = blockIdx.x * blockDim.x + threadIdx.x;
    if (t >= 65536) return;
    const int lane = t & 31;
    const int p    = (t >> 5) & 1;
    const int w    = (t >> 6) & 3;
    const int kc   = (t >> 8) & 15;
    const int nc   = (t >> 12) & 7;
    const int d    = (t >> 15) & 1;
    const float* U = d ? U_b : U_f;
    const int l4 = lane & 3, ld4 = lane >> 2;
    const int o8 = ld4;
    const int gate = (o8 & 1) + 2 * (o8 >> 2);
    const int uSel = (o8 >> 1) & 1;
    unsigned vals[4];
#pragma unroll
    for (int i = 0; i < 4; i++) {
        const int ns = 2 * p + (i >> 1);
        const int k0 = kc * 16 + l4 * 2 + (i & 1) * 8;
        const int j  = nc * 32 + w * 8 + ns * 2 + uSel;
        const int col = gate * 256 + j;
        unsigned h0 = (unsigned)__half_as_ushort(__float2half_rn(U[k0 * 1024 + col]));
        unsigned h1 = (unsigned)__half_as_ushort(__float2half_rn(U[(k0 + 1) * 1024 + col]));
        vals[i] = h0 | (h1 << 16);
    }
    g_Uf16[t] = make_uint4(vals[0], vals[1], vals[2], vals[3]);
}

// ---------------- kernel 3: persistent recurrence --------------------------
// grid = 128 = 32 clusters of 4; cluster = (d, mg), rank = ncp.
// CTA = 16 rows x 256 gate cols; block = 256 = 8 warps (tile wid>>2, w_nl wid&3).
// U weights live entirely in REGISTERS (128 regs/thread). Data exchange via L2,
// notification via cluster mbarriers (2-phase, count 32 = 4 CTAs x 8 warps).
__global__ void __launch_bounds__(256, 1) __cluster_dims__(4, 1, 1)
lstm_kernel(const int* __restrict__ token_ids) {
    __shared__ __align__(16) unsigned long long mbar[2];   // [parity]

    const int tid = threadIdx.x;
    const int bx  = blockIdx.x;
    const int d   = bx >> 6;
    const int mg  = (bx >> 2) & 15;
    const int ncp = bx & 3;            // == cluster rank
    const int wid = tid >> 5;
    const int w_nl = wid & 3;
    const int l   = tid & 31;
    const int l4  = l & 3, ld4 = l >> 2;
    const bool hi4 = (l4 >= 2);

    // ---- load this warp's U slice into registers (constant all steps)
    const int nc = ncp * 2 + (wid >> 2);
    uint4 Breg[16][2];
    {
        const uint4* ub = &g_Uf16[(d * 8 + nc) * 4096];
#pragma unroll
        for (int kc = 0; kc < 16; kc++)
#pragma unroll
            for (int p = 0; p < 2; p++)
                Breg[kc][p] = __ldg(ub + ((kc * 4 + w_nl) * 2 + p) * 32 + l);
    }

    const uint32_t barBase = smem_u32(&mbar[0]);
    if (tid == 0) {
#pragma unroll
        for (int i = 0; i < 2; i++)
            asm volatile("mbarrier.init.shared.b64 [%0], %1;"
                         :: "r"(barBase + i * 8), "r"(32u) : "memory");
    }
    __syncthreads();
    asm volatile("barrier.cluster.arrive.aligned;" ::: "memory");
    asm volatile("barrier.cluster.wait.aligned;" ::: "memory");

    uint32_t rbar[4];
#pragma unroll
    for (int r = 0; r < 4; r++)
        asm("mapa.shared::cluster.u32 %0, %1, %2;" : "=r"(rbar[r]) : "r"(barBase), "r"(r));

    float cs[4], hs[4];
#pragma unroll
    for (int a = 0; a < 4; a++) { cs[a] = 0.f; hs[a] = 0.f; }

    const int rbase = mg * 16;
    const int kcP = ncp * 4 + (wid >> 1);     // produced k-chunk (global idx)
    const int regP = (hi4 ? 1 : 0) + ((wid & 1) ? 2 : 0);

    for (int s = 0; s < T_; s++) {
        const int tt = d ? (T_ - 1 - s) : s;

        const int t0 = token_ids[(rbase + ld4) * T_ + tt];
        const int t1 = token_ids[(rbase + ld4 + 8) * T_ + tt];

        float c_[4][4];
        {
            const float* ea = g_embWp[d][t0] + ncp * 256 + wid * 32;
            const float* eb = g_embWp[d][t1] + ncp * 256 + wid * 32;
#pragma unroll
            for (int ns = 0; ns < 4; ns++) {
                const int cb = ns * 8 + 2 * l4;
                float2 x0 = *(const float2*)(ea + cb);
                float2 x1 = *(const float2*)(eb + cb);
                c_[ns][0] = x0.x; c_[ns][1] = x0.y;
                c_[ns][2] = x1.x; c_[ns][3] = x1.y;
            }
        }

        if (s > 0) {
            const int par = (s - 1) & 1;
            const unsigned ph = (unsigned)(((s - 1) >> 1) & 1);
            mbar_wait_cluster(barBase + par * 8, ph);

            const uint4* gsrc = g_HA4 + ((d * 2 + par) * 16 + mg) * 512;

            // rolling double-buffered A loads (groups of 4 chunks), fixed order
            uint4 A[2][4];
#pragma unroll
            for (int i = 0; i < 4; i++) A[0][i] = __ldcg(gsrc + i * 32 + l);
#pragma unroll
            for (int g = 0; g < 4; g++) {
                if (g < 3) {
#pragma unroll
                    for (int i = 0; i < 4; i++)
                        A[(g + 1) & 1][i] = __ldcg(gsrc + ((g + 1) * 4 + i) * 32 + l);
                }
#pragma unroll
                for (int q = 0; q < 4; q++) {
                    const int kc = g * 4 + q;
                    const unsigned* Ar = (const unsigned*)&A[g & 1][q];
                    mma16(c_[0], Ar, Breg[kc][0].x, Breg[kc][0].y);
                    mma16(c_[1], Ar, Breg[kc][0].z, Breg[kc][0].w);
                    mma16(c_[2], Ar, Breg[kc][1].x, Breg[kc][1].y);
                    mma16(c_[3], Ar, Breg[kc][1].z, Breg[kc][1].w);
                }
            }
        }

        // ---- elementwise (register state) + fp16 pack + publish to L2
        unsigned* hbase = (unsigned*)(g_HA4 + ((d * 2 + (s & 1)) * 16 + mg) * 512);
        const bool msk = (hi4 ? t1 : t0) != 0;
#pragma unroll
        for (int ns = 0; ns < 4; ns++) {
            float s0 = hi4 ? c_[ns][0] : c_[ns][2];
            float s1 = hi4 ? c_[ns][1] : c_[ns][3];
            float q0 = __shfl_xor_sync(0xffffffffu, s0, 2);
            float q1 = __shfl_xor_sync(0xffffffffu, s1, 2);
            const float zi = hi4 ? q0 : c_[ns][0];
            const float zf = hi4 ? q1 : c_[ns][1];
            const float zg = hi4 ? c_[ns][2] : q0;
            const float zo = hi4 ? c_[ns][3] : q1;
            const float ii = sigx(zi);
            const float ff = sigx(zf);
            const float gg = tapx(zg);
            const float oo = sigx(zo);
            const float cn = fmaf(ff, cs[ns], ii * gg);
            const float hn = oo * tapx(cn);
            const float cn2 = msk ? cn : cs[ns];
            const float hn2 = msk ? hn : hs[ns];
            cs[ns] = cn2;
            hs[ns] = hn2;
            unsigned hb = (unsigned)__half_as_ushort(__float2half_rn(hn2));
            unsigned pb = __shfl_xor_sync(0xffffffffu, hb, 1);
            if ((l4 & 1) == 0) {
                unsigned word = (hb & 0xffffu) | (pb << 16);
                hbase[(kcP * 32 + ld4 * 4 + ns) * 4 + regP] = word;
            }
        }
        __syncwarp();   // memory-orders all lanes' STGs before lane 0's release-arrives
        if (l == 0 && s + 1 < T_) {
            const unsigned bofs = (unsigned)((s & 1) * 8);
#pragma unroll
            for (int r = 0; r < 4; r++)
                asm volatile("mbarrier.arrive.release.cluster.shared::cluster.b64 _, [%0];"
                             :: "r"(rbar[r] + bofs) : "memory");
        }
        __syncthreads();  // intra-CTA parity-reuse protection + CTA-scope fence
    }

    asm volatile("barrier.cluster.arrive.aligned;" ::: "memory");
    asm volatile("barrier.cluster.wait.aligned;" ::: "memory");
}

// ---------------- kernel 4: output projection (1 warp / batch row) ---------
__global__ void output_kernel(const float* __restrict__ Wout, const float* __restrict__ bout,
                              float* __restrict__ out) {
    const int b = blockIdx.x;
    const int l = threadIdx.x;
    const int mg = b >> 4, r = b & 15;
    const unsigned* hf = (const unsigned*)(g_HA4 + ((0 * 2 + 1) * 16 + mg) * 512);
    const unsigned* hr = (const unsigned*)(g_HA4 + ((1 * 2 + 1) * 16 + mg) * 512);
    float a0 = 0.f, a1 = 0.f;
#pragma unroll
    for (int i = 0; i < 8; i++) {
        const int k = l * 8 + i;
        const int kc = k >> 4, kj = k & 15;
        const int lc = (r & 7) * 4 + ((kj & 7) >> 1);
        const int reg = ((r >= 8) ? 1 : 0) + ((kj >= 8) ? 2 : 0);
        const int off = (kc * 32 + lc) * 4 + reg;
        unsigned uf = hf[off], ur = hr[off];
        unsigned sf = (kj & 1) ? (uf >> 16) : (uf & 0xffffu);
        unsigned sr = (kj & 1) ? (ur >> 16) : (ur & 0xffffu);
        const float f  = __half2float(__ushort_as_half((unsigned short)sf));
        const float rr = __half2float(__ushort_as_half((unsigned short)sr));
        a0 += f * Wout[2 * k]     + rr * Wout[2 * (H_ + k)];
        a1 += f * Wout[2 * k + 1] + rr * Wout[2 * (H_ + k) + 1];
    }
#pragma unroll
    for (int o = 16; o; o >>= 1) {
        a0 += __shfl_down_sync(0xffffffffu, a0, o);
        a1 += __shfl_down_sync(0xffffffffu, a1, o);
    }
    if (l == 0) {
        out[2 * b]     = a0 + bout[0];
        out[2 * b + 1] = a1 + bout[1];
    }
}

// ---------------- launch ----------------------------------------------------
extern "C" void kernel_launch(void* const* d_in, const int* in_sizes, int n_in,
                              void* d_out, int out_size) {
    const int*   tok   = (const int*)d_in[0];
    const float* emb   = (const float*)d_in[1];
    const float* W_f   = (const float*)d_in[2];
    const float* U_f   = (const float*)d_in[3];
    const float* b_f   = (const float*)d_in[4];
    const float* W_b   = (const float*)d_in[5];
    const float* U_b   = (const float*)d_in[6];
    const float* b_b   = (const float*)d_in[7];
    const float* W_out = (const float*)d_in[8];
    const float* b_out = (const float*)d_in[9];
    float* out = (float*)d_out;

    precompute_embW<<<dim3(16, 32, 2), 256>>>(emb, W_f, b_f, W_b, b_b);
    build_Uf16<<<256, 256>>>(U_f, U_b);
    lstm_kernel<<<128, 256>>>(tok);
    output_kernel<<<B_, 32>>>(W_out, b_out, out);
}